// round 5
// baseline (speedup 1.0000x reference)
#include <cuda_runtime.h>

// Problem shape (fixed by the dataset)
static constexpr int B_TOT = 65536;  // batches
static constexpr int NATOM = 256;    // atoms per frame
static constexpr int A_SEL = 64;     // align indices
static constexpr int M_SEL = 128;    // nn indices
static constexpr int WARPS = 8;      // batches per block (one warp each)
static constexpr int ROWF  = NATOM * 3;  // 768 floats per traj row

__global__ void __launch_bounds__(256, 5)
kabsch_align_kernel(const float* __restrict__ traj,
                    const float* __restrict__ ref_pos,
                    const int*   __restrict__ align_idx,
                    const int*   __restrict__ nn_idx,
                    float*       __restrict__ out)
{
    __shared__ float s_ref[A_SEL * 3];   // centered reference selection
    __shared__ float s_mean[3];
    __shared__ float s_Mc[WARPS][12];    // M (9) + centroid sum (3) per batch
    __shared__ float s_Rc[WARPS][12];    // R (9) + centroid (3) per batch

    const int tid  = threadIdx.x;
    const int w    = tid >> 5;
    const int lane = tid & 31;

    const int b = blockIdx.x * WARPS + w;
    const float* tb = traj + (size_t)b * ROWF;

    // ---- load indices directly (coalesced, no barrier dependency) ----
    const int a0 = align_idx[lane];
    const int a1 = align_idx[32 + lane];
    int nn[4];
    #pragma unroll
    for (int k = 0; k < 4; k++) nn[k] = nn_idx[k * 32 + lane];

    // ---- issue ALL gathers up front: 18 loads in flight (align + nn) ----
    // Consecutive lanes hit consecutive sorted indices => small line windows.
    float ax0 = tb[a0 * 3 + 0], ax1 = tb[a0 * 3 + 1], ax2 = tb[a0 * 3 + 2];
    float bx0 = tb[a1 * 3 + 0], bx1 = tb[a1 * 3 + 1], bx2 = tb[a1 * 3 + 2];
    float nx[12];
    #pragma unroll
    for (int k = 0; k < 4; k++) {
        int a = nn[k];
        nx[k * 3 + 0] = tb[a * 3 + 0];
        nx[k * 3 + 1] = tb[a * 3 + 1];
        nx[k * 3 + 2] = tb[a * 3 + 2];
    }

    // ---- block prologue: centered reference (overlaps the loads above) ----
    if (tid < A_SEL * 3) {
        int n = tid / 3, j = tid - n * 3;
        s_ref[tid] = ref_pos[align_idx[n] * 3 + j];
    }
    __syncthreads();
    if (tid < 3) {
        float s = 0.f;
        #pragma unroll
        for (int n = 0; n < A_SEL; n++) s += s_ref[n * 3 + tid];
        s_mean[tid] = s * (1.0f / A_SEL);
    }
    __syncthreads();
    if (tid < A_SEL * 3) s_ref[tid] -= s_mean[tid % 3];
    __syncthreads();

    // ---- phase 1: accumulate M and centroid from the two align atoms ----
    float r0 = s_ref[lane * 3 + 0];
    float r1 = s_ref[lane * 3 + 1];
    float r2 = s_ref[lane * 3 + 2];
    float q0 = s_ref[(32 + lane) * 3 + 0];
    float q1 = s_ref[(32 + lane) * 3 + 1];
    float q2 = s_ref[(32 + lane) * 3 + 2];

    float c0 = ax0 + bx0, c1 = ax1 + bx1, c2 = ax2 + bx2;
    float m00 = ax0 * r0 + bx0 * q0;
    float m01 = ax0 * r1 + bx0 * q1;
    float m02 = ax0 * r2 + bx0 * q2;
    float m10 = ax1 * r0 + bx1 * q0;
    float m11 = ax1 * r1 + bx1 * q1;
    float m12 = ax1 * r2 + bx1 * q2;
    float m20 = ax2 * r0 + bx2 * q0;
    float m21 = ax2 * r1 + bx2 * q1;
    float m22 = ax2 * r2 + bx2 * q2;

    #pragma unroll
    for (int o = 16; o > 0; o >>= 1) {
        m00 += __shfl_xor_sync(0xffffffffu, m00, o);
        m01 += __shfl_xor_sync(0xffffffffu, m01, o);
        m02 += __shfl_xor_sync(0xffffffffu, m02, o);
        m10 += __shfl_xor_sync(0xffffffffu, m10, o);
        m11 += __shfl_xor_sync(0xffffffffu, m11, o);
        m12 += __shfl_xor_sync(0xffffffffu, m12, o);
        m20 += __shfl_xor_sync(0xffffffffu, m20, o);
        m21 += __shfl_xor_sync(0xffffffffu, m21, o);
        m22 += __shfl_xor_sync(0xffffffffu, m22, o);
        c0  += __shfl_xor_sync(0xffffffffu, c0,  o);
        c1  += __shfl_xor_sync(0xffffffffu, c1,  o);
        c2  += __shfl_xor_sync(0xffffffffu, c2,  o);
    }
    if (lane == 0) {
        s_Mc[w][0] = m00; s_Mc[w][1] = m01; s_Mc[w][2] = m02;
        s_Mc[w][3] = m10; s_Mc[w][4] = m11; s_Mc[w][5] = m12;
        s_Mc[w][6] = m20; s_Mc[w][7] = m21; s_Mc[w][8] = m22;
        s_Mc[w][9] = c0;  s_Mc[w][10] = c1; s_Mc[w][11] = c2;
    }
    __syncthreads();

    // ---- phase 2: 8 solves in parallel (lanes 0..7 of warp 0) ----
    if (tid < WARPS) {
        float M0 = s_Mc[tid][0], M1 = s_Mc[tid][1], M2 = s_Mc[tid][2];
        float M3 = s_Mc[tid][3], M4 = s_Mc[tid][4], M5 = s_Mc[tid][5];
        float M6 = s_Mc[tid][6], M7 = s_Mc[tid][7], M8 = s_Mc[tid][8];

        // Bsym = M^T M (6 unique entries)
        float b00 = M0*M0 + M3*M3 + M6*M6;
        float b01 = M0*M1 + M3*M4 + M6*M7;
        float b02 = M0*M2 + M3*M5 + M6*M8;
        float b11 = M1*M1 + M4*M4 + M7*M7;
        float b12 = M1*M2 + M4*M5 + M7*M8;
        float b22 = M2*M2 + M5*M5 + M8*M8;

        // V = I (v[row][col])
        float v00 = 1.f, v01 = 0.f, v02 = 0.f;
        float v10 = 0.f, v11 = 1.f, v12 = 0.f;
        float v20 = 0.f, v21 = 0.f, v22 = 1.f;

        #pragma unroll
        for (int sweep = 0; sweep < 3; sweep++) {
            // rotate (0,1)
            {
                float apq = b01;
                if (fabsf(apq) > 1e-12f * (fabsf(b00) + fabsf(b11)) + 1e-30f) {
                    float tau = __fdividef((b11 - b00) * 0.5f, apq);
                    float t   = copysignf(1.0f, tau) *
                                __fdividef(1.0f, fabsf(tau) + sqrtf(1.0f + tau * tau));
                    float cc  = rsqrtf(1.0f + t * t);
                    float ss  = t * cc;
                    b00 -= t * apq; b11 += t * apq; b01 = 0.f;
                    float t02 = b02, t12 = b12;
                    b02 = cc * t02 - ss * t12;
                    b12 = ss * t02 + cc * t12;
                    float a, bb;
                    a = v00; bb = v01; v00 = cc * a - ss * bb; v01 = ss * a + cc * bb;
                    a = v10; bb = v11; v10 = cc * a - ss * bb; v11 = ss * a + cc * bb;
                    a = v20; bb = v21; v20 = cc * a - ss * bb; v21 = ss * a + cc * bb;
                }
            }
            // rotate (0,2)
            {
                float apq = b02;
                if (fabsf(apq) > 1e-12f * (fabsf(b00) + fabsf(b22)) + 1e-30f) {
                    float tau = __fdividef((b22 - b00) * 0.5f, apq);
                    float t   = copysignf(1.0f, tau) *
                                __fdividef(1.0f, fabsf(tau) + sqrtf(1.0f + tau * tau));
                    float cc  = rsqrtf(1.0f + t * t);
                    float ss  = t * cc;
                    b00 -= t * apq; b22 += t * apq; b02 = 0.f;
                    float t01 = b01, t12 = b12;
                    b01 = cc * t01 - ss * t12;
                    b12 = ss * t01 + cc * t12;
                    float a, bb;
                    a = v00; bb = v02; v00 = cc * a - ss * bb; v02 = ss * a + cc * bb;
                    a = v10; bb = v12; v10 = cc * a - ss * bb; v12 = ss * a + cc * bb;
                    a = v20; bb = v22; v20 = cc * a - ss * bb; v22 = ss * a + cc * bb;
                }
            }
            // rotate (1,2)
            {
                float apq = b12;
                if (fabsf(apq) > 1e-12f * (fabsf(b11) + fabsf(b22)) + 1e-30f) {
                    float tau = __fdividef((b22 - b11) * 0.5f, apq);
                    float t   = copysignf(1.0f, tau) *
                                __fdividef(1.0f, fabsf(tau) + sqrtf(1.0f + tau * tau));
                    float cc  = rsqrtf(1.0f + t * t);
                    float ss  = t * cc;
                    b11 -= t * apq; b22 += t * apq; b12 = 0.f;
                    float t01 = b01, t02 = b02;
                    b01 = cc * t01 - ss * t02;
                    b02 = ss * t01 + cc * t02;
                    float a, bb;
                    a = v01; bb = v02; v01 = cc * a - ss * bb; v02 = ss * a + cc * bb;
                    a = v11; bb = v12; v11 = cc * a - ss * bb; v12 = ss * a + cc * bb;
                    a = v21; bb = v22; v21 = cc * a - ss * bb; v22 = ss * a + cc * bb;
                }
            }
        }

        // sort eigenpairs descending (columns of V follow)
        float tf;
        if (b00 < b11) { tf=b00; b00=b11; b11=tf;
                         tf=v00; v00=v01; v01=tf;
                         tf=v10; v10=v11; v11=tf;
                         tf=v20; v20=v21; v21=tf; }
        if (b00 < b22) { tf=b00; b00=b22; b22=tf;
                         tf=v00; v00=v02; v02=tf;
                         tf=v10; v10=v12; v12=tf;
                         tf=v20; v20=v22; v22=tf; }
        if (b11 < b22) { tf=b11; b11=b22; b22=tf;
                         tf=v01; v01=v02; v02=tf;
                         tf=v11; v11=v12; v12=tf;
                         tf=v21; v21=v22; v22=tf; }

        // u0 = normalize(M v0), u1 = normalize(M v1 orthogonalized), u2 = u0 x u1
        float u00 = M0*v00 + M1*v10 + M2*v20;
        float u01 = M3*v00 + M4*v10 + M5*v20;
        float u02 = M6*v00 + M7*v10 + M8*v20;
        float inv = rsqrtf(u00*u00 + u01*u01 + u02*u02 + 1e-30f);
        u00 *= inv; u01 *= inv; u02 *= inv;

        float u10 = M0*v01 + M1*v11 + M2*v21;
        float u11 = M3*v01 + M4*v11 + M5*v21;
        float u12 = M6*v01 + M7*v11 + M8*v21;
        float dp = u00*u10 + u01*u11 + u02*u12;
        u10 -= dp * u00; u11 -= dp * u01; u12 -= dp * u02;
        inv = rsqrtf(u10*u10 + u11*u11 + u12*u12 + 1e-30f);
        u10 *= inv; u11 *= inv; u12 *= inv;

        float u20 = u01*u12 - u02*u11;
        float u21 = u02*u10 - u00*u12;
        float u22 = u00*u11 - u01*u10;

        // third reference column = v0 x v1 (forces det(R)=+1 == Kabsch sign fix)
        float w0 = v10*v21 - v20*v11;
        float w1 = v20*v01 - v00*v21;
        float w2 = v00*v11 - v10*v01;

        // R[i][j] = u0[i]*v0[j] + u1[i]*v1[j] + u2[i]*w[j]
        s_Rc[tid][0] = u00*v00 + u10*v01 + u20*w0;
        s_Rc[tid][1] = u00*v10 + u10*v11 + u20*w1;
        s_Rc[tid][2] = u00*v20 + u10*v21 + u20*w2;
        s_Rc[tid][3] = u01*v00 + u11*v01 + u21*w0;
        s_Rc[tid][4] = u01*v10 + u11*v11 + u21*w1;
        s_Rc[tid][5] = u01*v20 + u11*v21 + u21*w2;
        s_Rc[tid][6] = u02*v00 + u12*v01 + u22*w0;
        s_Rc[tid][7] = u02*v10 + u12*v11 + u22*w1;
        s_Rc[tid][8] = u02*v20 + u12*v21 + u22*w2;
        s_Rc[tid][9]  = s_Mc[tid][9]  * (1.0f / A_SEL);
        s_Rc[tid][10] = s_Mc[tid][10] * (1.0f / A_SEL);
        s_Rc[tid][11] = s_Mc[tid][11] * (1.0f / A_SEL);
    }
    __syncthreads();

    // ---- phase 3: rotate the 12 register-resident nn coords; coalesced STG ----
    float R00 = s_Rc[w][0], R01 = s_Rc[w][1], R02 = s_Rc[w][2];
    float R10 = s_Rc[w][3], R11 = s_Rc[w][4], R12 = s_Rc[w][5];
    float R20 = s_Rc[w][6], R21 = s_Rc[w][7], R22 = s_Rc[w][8];
    float cx  = s_Rc[w][9], cy  = s_Rc[w][10], cz = s_Rc[w][11];

    float* ob = out + (size_t)b * (M_SEL * 3);
    #pragma unroll
    for (int k = 0; k < 4; k++) {
        int m = k * 32 + lane;
        float x0 = nx[k * 3 + 0] - cx;
        float x1 = nx[k * 3 + 1] - cy;
        float x2 = nx[k * 3 + 2] - cz;
        ob[m * 3 + 0] = x0 * R00 + x1 * R10 + x2 * R20;
        ob[m * 3 + 1] = x0 * R01 + x1 * R11 + x2 * R21;
        ob[m * 3 + 2] = x0 * R02 + x1 * R12 + x2 * R22;
    }
}

extern "C" void kernel_launch(void* const* d_in, const int* in_sizes, int n_in,
                              void* d_out, int out_size)
{
    const float* traj      = (const float*)d_in[0];
    const float* ref_pos   = (const float*)d_in[1];
    const int*   align_idx = (const int*)d_in[2];
    const int*   nn_idx    = (const int*)d_in[3];
    float*       out       = (float*)d_out;

    dim3 grid(B_TOT / WARPS);
    dim3 block(256);
    kabsch_align_kernel<<<grid, block>>>(traj, ref_pos, align_idx, nn_idx, out);
}

// round 6
// speedup vs baseline: 1.2321x; 1.2321x over previous
#include <cuda_runtime.h>

// Problem shape (fixed by the dataset)
static constexpr int B_TOT = 65536;  // batches
static constexpr int NATOM = 256;    // atoms per frame
static constexpr int A_SEL = 64;     // align indices
static constexpr int M_SEL = 128;    // nn indices
static constexpr int WARPS = 8;      // batches per block (one warp each)
static constexpr int ROWF  = NATOM * 3;  // 768 floats per traj row

__global__ void __launch_bounds__(256, 6)
kabsch_align_kernel(const float* __restrict__ traj,
                    const float* __restrict__ ref_pos,
                    const int*   __restrict__ align_idx,
                    const int*   __restrict__ nn_idx,
                    float*       __restrict__ out)
{
    __shared__ float s_ref[A_SEL * 3];   // centered reference selection
    __shared__ float s_Mc[WARPS][12];    // M (9) + centroid sum (3) per batch
    __shared__ float s_Rc[WARPS][12];    // R (9) + centroid (3) per batch

    const int tid  = threadIdx.x;
    const int w    = tid >> 5;
    const int lane = tid & 31;

    const int b = blockIdx.x * WARPS + w;
    const float* tb = traj + (size_t)b * ROWF;

    // ---- align indices straight from gmem (L1/L2-hot, no barrier dep) ----
    const int a0 = align_idx[lane];
    const int a1 = align_idx[32 + lane];

    // ---- phase 1 gathers issue immediately; consecutive lanes hit
    //      consecutive sorted indices => small line windows ----
    float ax0 = tb[a0 * 3 + 0], ax1 = tb[a0 * 3 + 1], ax2 = tb[a0 * 3 + 2];
    float bx0 = tb[a1 * 3 + 0], bx1 = tb[a1 * 3 + 1], bx2 = tb[a1 * 3 + 2];

    // ---- warp 7 builds the centered reference selection (one barrier) ----
    if (w == 7) {
        float p0 = ref_pos[a0 * 3 + 0];
        float p1 = ref_pos[a0 * 3 + 1];
        float p2 = ref_pos[a0 * 3 + 2];
        float q0 = ref_pos[a1 * 3 + 0];
        float q1 = ref_pos[a1 * 3 + 1];
        float q2 = ref_pos[a1 * 3 + 2];
        float s0 = p0 + q0, s1 = p1 + q1, s2 = p2 + q2;
        #pragma unroll
        for (int o = 16; o > 0; o >>= 1) {
            s0 += __shfl_xor_sync(0xffffffffu, s0, o);
            s1 += __shfl_xor_sync(0xffffffffu, s1, o);
            s2 += __shfl_xor_sync(0xffffffffu, s2, o);
        }
        s0 *= (1.0f / A_SEL); s1 *= (1.0f / A_SEL); s2 *= (1.0f / A_SEL);
        s_ref[lane * 3 + 0] = p0 - s0;
        s_ref[lane * 3 + 1] = p1 - s1;
        s_ref[lane * 3 + 2] = p2 - s2;
        s_ref[(32 + lane) * 3 + 0] = q0 - s0;
        s_ref[(32 + lane) * 3 + 1] = q1 - s1;
        s_ref[(32 + lane) * 3 + 2] = q2 - s2;
    }
    __syncthreads();

    // ---- phase 1: accumulate M and centroid ----
    float r0 = s_ref[lane * 3 + 0];
    float r1 = s_ref[lane * 3 + 1];
    float r2 = s_ref[lane * 3 + 2];
    float q0 = s_ref[(32 + lane) * 3 + 0];
    float q1 = s_ref[(32 + lane) * 3 + 1];
    float q2 = s_ref[(32 + lane) * 3 + 2];

    float c0 = ax0 + bx0, c1 = ax1 + bx1, c2 = ax2 + bx2;
    float m00 = ax0 * r0 + bx0 * q0;
    float m01 = ax0 * r1 + bx0 * q1;
    float m02 = ax0 * r2 + bx0 * q2;
    float m10 = ax1 * r0 + bx1 * q0;
    float m11 = ax1 * r1 + bx1 * q1;
    float m12 = ax1 * r2 + bx1 * q2;
    float m20 = ax2 * r0 + bx2 * q0;
    float m21 = ax2 * r1 + bx2 * q1;
    float m22 = ax2 * r2 + bx2 * q2;

    #pragma unroll
    for (int o = 16; o > 0; o >>= 1) {
        m00 += __shfl_xor_sync(0xffffffffu, m00, o);
        m01 += __shfl_xor_sync(0xffffffffu, m01, o);
        m02 += __shfl_xor_sync(0xffffffffu, m02, o);
        m10 += __shfl_xor_sync(0xffffffffu, m10, o);
        m11 += __shfl_xor_sync(0xffffffffu, m11, o);
        m12 += __shfl_xor_sync(0xffffffffu, m12, o);
        m20 += __shfl_xor_sync(0xffffffffu, m20, o);
        m21 += __shfl_xor_sync(0xffffffffu, m21, o);
        m22 += __shfl_xor_sync(0xffffffffu, m22, o);
        c0  += __shfl_xor_sync(0xffffffffu, c0,  o);
        c1  += __shfl_xor_sync(0xffffffffu, c1,  o);
        c2  += __shfl_xor_sync(0xffffffffu, c2,  o);
    }
    if (lane == 0) {
        s_Mc[w][0] = m00; s_Mc[w][1] = m01; s_Mc[w][2] = m02;
        s_Mc[w][3] = m10; s_Mc[w][4] = m11; s_Mc[w][5] = m12;
        s_Mc[w][6] = m20; s_Mc[w][7] = m21; s_Mc[w][8] = m22;
        s_Mc[w][9] = c0;  s_Mc[w][10] = c1; s_Mc[w][11] = c2;
    }
    __syncthreads();

    // ---- phase 2: 8 solves in parallel (lanes 0..7 of warp 0) ----
    if (tid < WARPS) {
        float M0 = s_Mc[tid][0], M1 = s_Mc[tid][1], M2 = s_Mc[tid][2];
        float M3 = s_Mc[tid][3], M4 = s_Mc[tid][4], M5 = s_Mc[tid][5];
        float M6 = s_Mc[tid][6], M7 = s_Mc[tid][7], M8 = s_Mc[tid][8];

        // Bsym = M^T M (6 unique entries)
        float b00 = M0*M0 + M3*M3 + M6*M6;
        float b01 = M0*M1 + M3*M4 + M6*M7;
        float b02 = M0*M2 + M3*M5 + M6*M8;
        float b11 = M1*M1 + M4*M4 + M7*M7;
        float b12 = M1*M2 + M4*M5 + M7*M8;
        float b22 = M2*M2 + M5*M5 + M8*M8;

        // V = I (v[row][col])
        float v00 = 1.f, v01 = 0.f, v02 = 0.f;
        float v10 = 0.f, v11 = 1.f, v12 = 0.f;
        float v20 = 0.f, v21 = 0.f, v22 = 1.f;

        #pragma unroll
        for (int sweep = 0; sweep < 3; sweep++) {
            // rotate (0,1)
            {
                float apq = b01;
                if (fabsf(apq) > 1e-12f * (fabsf(b00) + fabsf(b11)) + 1e-30f) {
                    float tau = __fdividef((b11 - b00) * 0.5f, apq);
                    float t   = copysignf(1.0f, tau) *
                                __fdividef(1.0f, fabsf(tau) + sqrtf(1.0f + tau * tau));
                    float cc  = rsqrtf(1.0f + t * t);
                    float ss  = t * cc;
                    b00 -= t * apq; b11 += t * apq; b01 = 0.f;
                    float t02 = b02, t12 = b12;
                    b02 = cc * t02 - ss * t12;
                    b12 = ss * t02 + cc * t12;
                    float a, bb;
                    a = v00; bb = v01; v00 = cc * a - ss * bb; v01 = ss * a + cc * bb;
                    a = v10; bb = v11; v10 = cc * a - ss * bb; v11 = ss * a + cc * bb;
                    a = v20; bb = v21; v20 = cc * a - ss * bb; v21 = ss * a + cc * bb;
                }
            }
            // rotate (0,2)
            {
                float apq = b02;
                if (fabsf(apq) > 1e-12f * (fabsf(b00) + fabsf(b22)) + 1e-30f) {
                    float tau = __fdividef((b22 - b00) * 0.5f, apq);
                    float t   = copysignf(1.0f, tau) *
                                __fdividef(1.0f, fabsf(tau) + sqrtf(1.0f + tau * tau));
                    float cc  = rsqrtf(1.0f + t * t);
                    float ss  = t * cc;
                    b00 -= t * apq; b22 += t * apq; b02 = 0.f;
                    float t01 = b01, t12 = b12;
                    b01 = cc * t01 - ss * t12;
                    b12 = ss * t01 + cc * t12;
                    float a, bb;
                    a = v00; bb = v02; v00 = cc * a - ss * bb; v02 = ss * a + cc * bb;
                    a = v10; bb = v12; v10 = cc * a - ss * bb; v12 = ss * a + cc * bb;
                    a = v20; bb = v22; v20 = cc * a - ss * bb; v22 = ss * a + cc * bb;
                }
            }
            // rotate (1,2)
            {
                float apq = b12;
                if (fabsf(apq) > 1e-12f * (fabsf(b11) + fabsf(b22)) + 1e-30f) {
                    float tau = __fdividef((b22 - b11) * 0.5f, apq);
                    float t   = copysignf(1.0f, tau) *
                                __fdividef(1.0f, fabsf(tau) + sqrtf(1.0f + tau * tau));
                    float cc  = rsqrtf(1.0f + t * t);
                    float ss  = t * cc;
                    b11 -= t * apq; b22 += t * apq; b12 = 0.f;
                    float t01 = b01, t02 = b02;
                    b01 = cc * t01 - ss * t02;
                    b02 = ss * t01 + cc * t02;
                    float a, bb;
                    a = v01; bb = v02; v01 = cc * a - ss * bb; v02 = ss * a + cc * bb;
                    a = v11; bb = v12; v11 = cc * a - ss * bb; v12 = ss * a + cc * bb;
                    a = v21; bb = v22; v21 = cc * a - ss * bb; v22 = ss * a + cc * bb;
                }
            }
        }

        // sort eigenpairs descending (columns of V follow)
        float tf;
        if (b00 < b11) { tf=b00; b00=b11; b11=tf;
                         tf=v00; v00=v01; v01=tf;
                         tf=v10; v10=v11; v11=tf;
                         tf=v20; v20=v21; v21=tf; }
        if (b00 < b22) { tf=b00; b00=b22; b22=tf;
                         tf=v00; v00=v02; v02=tf;
                         tf=v10; v10=v12; v12=tf;
                         tf=v20; v20=v22; v22=tf; }
        if (b11 < b22) { tf=b11; b11=b22; b22=tf;
                         tf=v01; v01=v02; v02=tf;
                         tf=v11; v11=v12; v12=tf;
                         tf=v21; v21=v22; v22=tf; }

        // u0 = normalize(M v0), u1 = normalize(M v1 orthogonalized), u2 = u0 x u1
        float u00 = M0*v00 + M1*v10 + M2*v20;
        float u01 = M3*v00 + M4*v10 + M5*v20;
        float u02 = M6*v00 + M7*v10 + M8*v20;
        float inv = rsqrtf(u00*u00 + u01*u01 + u02*u02 + 1e-30f);
        u00 *= inv; u01 *= inv; u02 *= inv;

        float u10 = M0*v01 + M1*v11 + M2*v21;
        float u11 = M3*v01 + M4*v11 + M5*v21;
        float u12 = M6*v01 + M7*v11 + M8*v21;
        float dp = u00*u10 + u01*u11 + u02*u12;
        u10 -= dp * u00; u11 -= dp * u01; u12 -= dp * u02;
        inv = rsqrtf(u10*u10 + u11*u11 + u12*u12 + 1e-30f);
        u10 *= inv; u11 *= inv; u12 *= inv;

        float u20 = u01*u12 - u02*u11;
        float u21 = u02*u10 - u00*u12;
        float u22 = u00*u11 - u01*u10;

        // third reference column = v0 x v1 (forces det(R)=+1 == Kabsch sign fix)
        float w0 = v10*v21 - v20*v11;
        float w1 = v20*v01 - v00*v21;
        float w2 = v00*v11 - v10*v01;

        // R[i][j] = u0[i]*v0[j] + u1[i]*v1[j] + u2[i]*w[j]
        s_Rc[tid][0] = u00*v00 + u10*v01 + u20*w0;
        s_Rc[tid][1] = u00*v10 + u10*v11 + u20*w1;
        s_Rc[tid][2] = u00*v20 + u10*v21 + u20*w2;
        s_Rc[tid][3] = u01*v00 + u11*v01 + u21*w0;
        s_Rc[tid][4] = u01*v10 + u11*v11 + u21*w1;
        s_Rc[tid][5] = u01*v20 + u11*v21 + u21*w2;
        s_Rc[tid][6] = u02*v00 + u12*v01 + u22*w0;
        s_Rc[tid][7] = u02*v10 + u12*v11 + u22*w1;
        s_Rc[tid][8] = u02*v20 + u12*v21 + u22*w2;
        s_Rc[tid][9]  = s_Mc[tid][9]  * (1.0f / A_SEL);
        s_Rc[tid][10] = s_Mc[tid][10] * (1.0f / A_SEL);
        s_Rc[tid][11] = s_Mc[tid][11] * (1.0f / A_SEL);
    }
    __syncthreads();

    // ---- phase 3: rotate 128 nn atoms; gathers hit L1 lines fetched by
    //      phase 1; indices straight from gmem (L1-hot) ----
    float R00 = s_Rc[w][0], R01 = s_Rc[w][1], R02 = s_Rc[w][2];
    float R10 = s_Rc[w][3], R11 = s_Rc[w][4], R12 = s_Rc[w][5];
    float R20 = s_Rc[w][6], R21 = s_Rc[w][7], R22 = s_Rc[w][8];
    float cx  = s_Rc[w][9], cy  = s_Rc[w][10], cz = s_Rc[w][11];

    float* ob = out + (size_t)b * (M_SEL * 3);
    #pragma unroll
    for (int k = 0; k < 4; k++) {
        int m = k * 32 + lane;
        int a = nn_idx[m];
        float x0 = tb[a * 3 + 0] - cx;
        float x1 = tb[a * 3 + 1] - cy;
        float x2 = tb[a * 3 + 2] - cz;
        ob[m * 3 + 0] = x0 * R00 + x1 * R10 + x2 * R20;
        ob[m * 3 + 1] = x0 * R01 + x1 * R11 + x2 * R21;
        ob[m * 3 + 2] = x0 * R02 + x1 * R12 + x2 * R22;
    }
}

extern "C" void kernel_launch(void* const* d_in, const int* in_sizes, int n_in,
                              void* d_out, int out_size)
{
    const float* traj      = (const float*)d_in[0];
    const float* ref_pos   = (const float*)d_in[1];
    const int*   align_idx = (const int*)d_in[2];
    const int*   nn_idx    = (const int*)d_in[3];
    float*       out       = (float*)d_out;

    dim3 grid(B_TOT / WARPS);
    dim3 block(256);
    kabsch_align_kernel<<<grid, block>>>(traj, ref_pos, align_idx, nn_idx, out);
}